// round 11
// baseline (speedup 1.0000x reference)
#include <cuda_runtime.h>
#include <cstdint>

// DSAttention, fp32 flash-attention, FFMA2 (f32x2) + cp.async double-buffered
// K/V tiles + float4-chunked GEMM2 (crossbar-minimal).
// B=2, L=S=2048, H=16, E=D=64.
// logits = 0.125*(tau[b]*(q.k) + delta[b,s]); out = softmax(logits) @ V

namespace {

constexpr int B_ = 2, L_ = 2048, S_ = 2048, H_ = 16, E_ = 64, D_ = 64;
constexpr int TM = 64;        // query rows per block
constexpr int TN = 64;        // key/value rows per tile
constexpr int STRIDE = 68;    // padded smem row stride (17 x float4)
constexpr int THREADS = 256;  // 16x16: ty=t>>4 rows, tx=t&15 cols
constexpr int NTILES = S_ / TN;

constexpr int TILE_F = TM * STRIDE;                       // 4352 floats per tile buffer
constexpr size_t SMEM_FLOATS = (size_t)TILE_F * 6 + 2 * TN; // Qs + Ks[2] + Vs[2] + Ps + dls[2]
constexpr size_t SMEM_BYTES  = SMEM_FLOATS * sizeof(float); // ~105 KB -> 2 blocks/SM

union F4U2 { float4 f; unsigned long long u[2]; };
union F4A  { float4 f; float a[4]; };

__device__ __forceinline__ unsigned long long fma2(
    unsigned long long a, unsigned long long b, unsigned long long c) {
    unsigned long long d;
    asm("fma.rn.f32x2 %0, %1, %2, %3;" : "=l"(d) : "l"(a), "l"(b), "l"(c));
    return d;
}
__device__ __forceinline__ unsigned long long mul2(
    unsigned long long a, unsigned long long b) {
    unsigned long long d;
    asm("mul.rn.f32x2 %0, %1, %2;" : "=l"(d) : "l"(a), "l"(b));
    return d;
}
__device__ __forceinline__ unsigned long long pack2(float lo, float hi) {
    unsigned long long d;
    asm("mov.b64 %0, {%1, %2};" : "=l"(d) : "f"(lo), "f"(hi));
    return d;
}
__device__ __forceinline__ float2 unpack2(unsigned long long v) {
    float2 r;
    asm("mov.b64 {%0, %1}, %2;" : "=f"(r.x), "=f"(r.y) : "l"(v));
    return r;
}

__device__ __forceinline__ void cp16(uint32_t dst, const void* src) {
    asm volatile("cp.async.cg.shared.global [%0], [%1], 16;" :: "r"(dst), "l"(src));
}
__device__ __forceinline__ void cp4(uint32_t dst, const void* src) {
    asm volatile("cp.async.ca.shared.global [%0], [%1], 4;" :: "r"(dst), "l"(src));
}
__device__ __forceinline__ void cp_commit() {
    asm volatile("cp.async.commit_group;" ::: "memory");
}
__device__ __forceinline__ void cp_wait0() {
    asm volatile("cp.async.wait_group 0;" ::: "memory");
}

__global__ __launch_bounds__(THREADS, 2) void dsattn_kernel(
    const float* __restrict__ Q, const float* __restrict__ K,
    const float* __restrict__ V, const float* __restrict__ Tau,
    const float* __restrict__ Delta, float* __restrict__ Out)
{
    extern __shared__ float sm[];
    float* Qs    = sm;                        // [TM][STRIDE]
    float* KsA[2]; KsA[0] = sm + TILE_F;     KsA[1] = sm + 2 * TILE_F;
    float* VsA[2]; VsA[0] = sm + 3 * TILE_F; VsA[1] = sm + 4 * TILE_F;
    float* Ps    = sm + 5 * TILE_F;           // [TM][STRIDE]
    float* dlsA  = Ps + TILE_F;               // [2][TN] raw delta

    const uint32_t smb = (uint32_t)__cvta_generic_to_shared(sm);
    const uint32_t ks_u[2] = { smb + (uint32_t)(TILE_F * 4),     smb + (uint32_t)(2 * TILE_F * 4) };
    const uint32_t vs_u[2] = { smb + (uint32_t)(3 * TILE_F * 4), smb + (uint32_t)(4 * TILE_F * 4) };
    const uint32_t dl_u    = smb + (uint32_t)(6 * TILE_F * 4);

    const int t  = threadIdx.x;
    const int ty = t >> 4;              // rows 4*ty .. 4*ty+3
    const int tx = t & 15;              // GEMM1 cols tx+16j; GEMM2/out cols 4tx..4tx+3
    const int bh = blockIdx.y;
    const int b  = bh / H_;
    const int h  = bh - b * H_;
    const int l0 = blockIdx.x * TM;

    const float qscale = 0.125f * Tau[b];
    const float* qb = Q + (((size_t)b * L_) * H_ + h) * E_;
    const float* kb = K + (((size_t)b * S_) * H_ + h) * E_;
    const float* vb = V + (((size_t)b * S_) * H_ + h) * D_;
    const float* db = Delta + (size_t)b * S_;

    const int fs = t >> 4;   // fill row base (idx = t + i*256 -> s = idx>>4 = fs + 16*i)
    const int fe = t & 15;   // fill float4 index

    // Prologue: Q tile (fold 0.125*tau) + async fill of stage 0
    #pragma unroll
    for (int i = 0; i < 4; ++i) {
        int m = fs + 16 * i;
        float4 a = *(const float4*)(qb + (size_t)(l0 + m) * (H_ * E_) + fe * 4);
        float* d = &Qs[m * STRIDE + fe * 4];
        d[0] = a.x * qscale; d[1] = a.y * qscale;
        d[2] = a.z * qscale; d[3] = a.w * qscale;
    }
    {
        #pragma unroll
        for (int i = 0; i < 4; ++i) {
            int s = fs + 16 * i;
            uint32_t off = (uint32_t)((s * STRIDE + fe * 4) * 4);
            cp16(ks_u[0] + off, kb + (size_t)s * (H_ * E_) + fe * 4);
            cp16(vs_u[0] + off, vb + (size_t)s * (H_ * D_) + fe * 4);
        }
        if (t < TN) cp4(dl_u + t * 4, db + t);
        cp_commit();
    }

    float mrow[4], lrow[4];
    unsigned long long acc2[4][2];   // [0]: cols {4tx,4tx+1}, [1]: {4tx+2,4tx+3}
    #pragma unroll
    for (int i = 0; i < 4; ++i) {
        mrow[i] = -1e30f; lrow[i] = 0.0f;
        acc2[i][0] = 0ull; acc2[i][1] = 0ull;
    }

    int cur = 0;
    for (int tile = 0; tile < NTILES; ++tile) {
        cp_wait0();
        __syncthreads();   // stage `cur` visible to all; prev GEMM2 done with Ps & other stage

        if (tile + 1 < NTILES) {           // async fill next stage
            int nxt = cur ^ 1;
            int s0n = (tile + 1) * TN;
            #pragma unroll
            for (int i = 0; i < 4; ++i) {
                int s = fs + 16 * i;
                uint32_t off = (uint32_t)((s * STRIDE + fe * 4) * 4);
                cp16(ks_u[nxt] + off, kb + (size_t)(s0n + s) * (H_ * E_) + fe * 4);
                cp16(vs_u[nxt] + off, vb + (size_t)(s0n + s) * (H_ * D_) + fe * 4);
            }
            if (t < TN) cp4(dl_u + (nxt * TN + t) * 4, db + s0n + t);
            cp_commit();
        }

        const float* Ks = KsA[cur];
        const float* Vs = VsA[cur];
        const float* dls = dlsA + cur * TN;

        // ---- GEMM1 (packed k-pairs): sc[i][j] = Qs[4ty+i] . Ks[tx+16j] ----
        unsigned long long sc2[4][4];
        #pragma unroll
        for (int i = 0; i < 4; ++i)
            #pragma unroll
            for (int j = 0; j < 4; ++j) sc2[i][j] = 0ull;

        #pragma unroll
        for (int k4 = 0; k4 < 16; ++k4) {
            F4U2 a[4], bb[4];
            #pragma unroll
            for (int i = 0; i < 4; ++i)
                a[i].f = *(const float4*)(&Qs[(4 * ty + i) * STRIDE + 4 * k4]);
            #pragma unroll
            for (int j = 0; j < 4; ++j)
                bb[j].f = *(const float4*)(&Ks[(tx + 16 * j) * STRIDE + 4 * k4]);
            #pragma unroll
            for (int i = 0; i < 4; ++i)
                #pragma unroll
                for (int j = 0; j < 4; ++j) {
                    sc2[i][j] = fma2(a[i].u[0], bb[j].u[0], sc2[i][j]);
                    sc2[i][j] = fma2(a[i].u[1], bb[j].u[1], sc2[i][j]);
                }
        }

        float sc[4][4];
        #pragma unroll
        for (int j = 0; j < 4; ++j) {
            float dl = 0.125f * dls[tx + 16 * j];
            #pragma unroll
            for (int i = 0; i < 4; ++i) {
                float2 p = unpack2(sc2[i][j]);
                sc[i][j] = p.x + p.y + dl;
            }
        }

        // ---- online softmax (row groups = contiguous 16-lane halves) ----
        #pragma unroll
        for (int i = 0; i < 4; ++i) {
            float mx = fmaxf(fmaxf(sc[i][0], sc[i][1]), fmaxf(sc[i][2], sc[i][3]));
            #pragma unroll
            for (int w = 1; w < 16; w <<= 1)
                mx = fmaxf(mx, __shfl_xor_sync(0xffffffffu, mx, w));
            float mn   = fmaxf(mrow[i], mx);
            float corr = __expf(mrow[i] - mn);
            mrow[i] = mn;

            float rs = 0.0f;
            #pragma unroll
            for (int j = 0; j < 4; ++j) {
                float p = __expf(sc[i][j] - mn);
                Ps[(4 * ty + i) * STRIDE + tx + 16 * j] = p;  // conflict-free scatter
                rs += p;
            }
            #pragma unroll
            for (int w = 1; w < 16; w <<= 1)
                rs += __shfl_xor_sync(0xffffffffu, rs, w);
            lrow[i] = lrow[i] * corr + rs;

            unsigned long long cp = pack2(corr, corr);
            acc2[i][0] = mul2(acc2[i][0], cp);
            acc2[i][1] = mul2(acc2[i][1], cp);
        }
        __syncthreads();

        // ---- GEMM2 (4-s chunks, float4 loads): acc += P[row][s]*V[s][4tx..] ----
        #pragma unroll 4
        for (int c = 0; c < TN / 4; ++c) {
            F4A  p4[4];
            F4U2 v4[4];
            #pragma unroll
            for (int i = 0; i < 4; ++i)
                p4[i].f = *(const float4*)(&Ps[(4 * ty + i) * STRIDE + 4 * c]);
            #pragma unroll
            for (int ss = 0; ss < 4; ++ss)
                v4[ss].f = *(const float4*)(&Vs[(4 * c + ss) * STRIDE + 4 * tx]);
            #pragma unroll
            for (int ss = 0; ss < 4; ++ss)
                #pragma unroll
                for (int i = 0; i < 4; ++i) {
                    unsigned long long pd = pack2(p4[i].a[ss], p4[i].a[ss]);
                    acc2[i][0] = fma2(pd, v4[ss].u[0], acc2[i][0]);
                    acc2[i][1] = fma2(pd, v4[ss].u[1], acc2[i][1]);
                }
        }

        cur ^= 1;
    }

    // Epilogue: normalize, store [B,L,H,D] as one float4 per row (coalesced)
    #pragma unroll
    for (int i = 0; i < 4; ++i) {
        float inv = 1.0f / lrow[i];
        size_t row = (((size_t)b * L_ + (l0 + 4 * ty + i)) * H_ + h) * (size_t)D_;
        float2 o0 = unpack2(acc2[i][0]);
        float2 o1 = unpack2(acc2[i][1]);
        float4 o;
        o.x = o0.x * inv; o.y = o0.y * inv;
        o.z = o1.x * inv; o.w = o1.y * inv;
        *(float4*)(&Out[row + 4 * tx]) = o;
    }
}

}  // namespace

extern "C" void kernel_launch(void* const* d_in, const int* /*in_sizes*/, int /*n_in*/,
                              void* d_out, int /*out_size*/) {
    const float* q     = (const float*)d_in[0];
    const float* k     = (const float*)d_in[1];
    const float* v     = (const float*)d_in[2];
    const float* tau   = (const float*)d_in[3];
    const float* delta = (const float*)d_in[4];
    // d_in[5] = attn_mask, unused (mask_flag=False)

    cudaFuncSetAttribute(dsattn_kernel,
                         cudaFuncAttributeMaxDynamicSharedMemorySize,
                         (int)SMEM_BYTES);

    dim3 grid(L_ / TM, B_ * H_);  // x = q-tile (fast): one (b,h)'s K/V stays hot in L2
    dsattn_kernel<<<grid, THREADS, SMEM_BYTES>>>(q, k, v, tau, delta, (float*)d_out);
}